// round 4
// baseline (speedup 1.0000x reference)
#include <cuda_runtime.h>
#include <cuda_fp16.h>

#define NN 50000
#define NE 800000
#define NG 1024
#define DIN 9
#define DD 64
#define SCAN_BLKS ((NN + 255) / 256)   // 196

// ---- scratch (static device globals) ----
__device__ __half2  g_h2 [NN*32];     // activations (post-tanh), fp16
__device__ __half2  g_hw2[NN*32];     // h @ W, fp16
__device__ float    g_aggx[NN*DIN];   // aggregated raw features (layer 0)
__device__ int      g_degi[NN];       // in-degree (no self loop)
__device__ float    g_dinv[NN];
__device__ int      g_rp  [NN];       // CSR row start
__device__ int      g_cur [NN];       // fill cursor
__device__ int2     g_ep  [NE];       // (src, bitcast norm)
__device__ int      g_bsum[256];
__device__ unsigned g_gmax[NG*DD];
__device__ float    g_gsum[NG*DD];
__device__ float    g_gcnt[NG];

__device__ __forceinline__ unsigned fkey(float f) {
    unsigned b = __float_as_uint(f);
    return (b & 0x80000000u) ? ~b : (b | 0x80000000u);
}
__device__ __forceinline__ float funkey(unsigned k) {
    unsigned b = (k & 0x80000000u) ? (k & 0x7FFFFFFFu) : ~k;
    return __uint_as_float(b);
}

__global__ void k_init() {
    int i = blockIdx.x * blockDim.x + threadIdx.x;
    if (i < NN) g_degi[i] = 0;
    if (i < NG*DD) { g_gmax[i] = 0u; g_gsum[i] = 0.0f; }
    if (i < NG) g_gcnt[i] = 0.0f;
}

__global__ void k_deg(const int4* __restrict__ dst4) {
    int e = blockIdx.x * blockDim.x + threadIdx.x;
    if (e >= NE/4) return;
    int4 d = dst4[e];
    atomicAdd(&g_degi[d.x], 1);
    atomicAdd(&g_degi[d.y], 1);
    atomicAdd(&g_degi[d.z], 1);
    atomicAdd(&g_degi[d.w], 1);
}

// per-block inclusive scan of degi -> rp (exclusive), block sums to g_bsum
__global__ void k_scan1() {
    __shared__ int sh[256];
    int t = threadIdx.x, i = blockIdx.x * 256 + t;
    int v = (i < NN) ? g_degi[i] : 0;
    sh[t] = v; __syncthreads();
    #pragma unroll
    for (int off = 1; off < 256; off <<= 1) {
        int u = (t >= off) ? sh[t - off] : 0;
        __syncthreads();
        sh[t] += u; __syncthreads();
    }
    if (i < NN) g_rp[i] = sh[t] - v;
    if (t == 255) g_bsum[blockIdx.x] = sh[255];
}

// fused: per-block prefix of bsum + apply + cursor/dinv init
__global__ void k_scan3() {
    __shared__ int sh[256];
    int t = threadIdx.x;
    int v = (t < SCAN_BLKS) ? g_bsum[t] : 0;
    sh[t] = v; __syncthreads();
    #pragma unroll
    for (int off = 1; off < 256; off <<= 1) {
        int u = (t >= off) ? sh[t - off] : 0;
        __syncthreads();
        sh[t] += u; __syncthreads();
    }
    int boff = (blockIdx.x > 0) ? sh[blockIdx.x - 1] : 0;
    int i = blockIdx.x * 256 + t;
    if (i < NN) {
        g_rp[i] += boff;
        g_cur[i] = 0;
        g_dinv[i] = rsqrtf(1.0f + (float)g_degi[i]);
    }
}

__global__ void k_fill(const int* __restrict__ src, const int* __restrict__ dst) {
    int e = blockIdx.x * blockDim.x + threadIdx.x;
    if (e >= NE) return;
    int d = dst[e], s = src[e];
    int pos = g_rp[d] + atomicAdd(&g_cur[d], 1);
    g_ep[pos] = make_int2(s, __float_as_int(g_dinv[s] * g_dinv[d]));
}

// layer-0 aggregation over raw fp32 features (9 dims)
__global__ void k_gather9(const float* __restrict__ x) {
    int t = blockIdx.x * blockDim.x + threadIdx.x;
    int n = t >> 4, c = t & 15;
    if (n >= NN || c >= DIN) return;
    int rp = g_rp[n], dg = g_degi[n];
    float dn = g_dinv[n];
    float acc = dn * dn * x[n*DIN + c];
    for (int j = 0; j < dg; j++) {
        int2 p = g_ep[rp + j];
        acc += __int_as_float(p.y) * x[p.x*DIN + c];
    }
    g_aggx[n*DIN + c] = acc;
}

// h0 = tanh(aggx @ W0 + b0) -> fp16; 8 nodes/block, lane computes 2 cols
__global__ void k_gemm0f(const float* __restrict__ W, const float* __restrict__ b) {
    __shared__ float Ws[DIN*DD];
    __shared__ float axs[8][DIN];
    int tid = threadIdx.x;
    for (int i = tid; i < DIN*DD; i += 256) Ws[i] = W[i];
    int nb = blockIdx.x * 8;
    if (tid < 8*DIN) {
        int r = tid / DIN, k = tid % DIN, n = nb + r;
        axs[r][k] = (n < NN) ? g_aggx[n*DIN + k] : 0.0f;
    }
    __syncthreads();
    int r = tid >> 5, l = tid & 31;
    int n = nb + r;
    if (n >= NN) return;
    int c0 = 2*l, c1 = 2*l + 1;
    float s0 = b[c0], s1 = b[c1];
    #pragma unroll
    for (int k = 0; k < DIN; k++) {
        float a = axs[r][k];
        s0 += a * Ws[k*DD + c0];
        s1 += a * Ws[k*DD + c1];
    }
    g_h2[n*32 + l] = __floats2half2_rn(tanhf(s0), tanhf(s1));
}

// hw = h @ W  (fp16 in, fp32 math, fp16 out). 32 nodes/block, 8 cols/thread.
__global__ void k_gemm64(const float* __restrict__ W) {
    __shared__ float Ws[DD*DD];           // 16 KB
    __shared__ __half2 hs[32][33];        // 32 nodes x 32 half2 (+pad)
    int tid = threadIdx.x;
    #pragma unroll
    for (int i = 0; i < 16; i++) Ws[tid + i*256] = W[tid + i*256];
    int nb = blockIdx.x * 32;
    #pragma unroll
    for (int i = 0; i < 4; i++) {
        int idx = tid + i*256;
        int r = idx >> 5, k2 = idx & 31;
        int n = nb + r;
        hs[r][k2] = (n < NN) ? g_h2[n*32 + k2] : __float2half2_rn(0.0f);
    }
    __syncthreads();
    int r = tid >> 3, q = tid & 7;
    int n = nb + r;
    if (n >= NN) return;
    float acc[8] = {0,0,0,0,0,0,0,0};
    #pragma unroll
    for (int k2 = 0; k2 < 32; k2++) {
        float2 hv = __half22float2(hs[r][k2]);
        const float* w0 = &Ws[(2*k2)*DD + q*8];
        const float* w1 = w0 + DD;
        #pragma unroll
        for (int j = 0; j < 8; j++) acc[j] += hv.x * w0[j] + hv.y * w1[j];
    }
    __half2 o[4];
    #pragma unroll
    for (int j = 0; j < 4; j++) o[j] = __floats2half2_rn(acc[2*j], acc[2*j+1]);
    *reinterpret_cast<uint4*>(&g_hw2[n*32 + q*4]) = *reinterpret_cast<uint4*>(o);
}

__device__ __forceinline__ void acc_row(float* acc, uint4 v, float w) {
    const __half2* hp = reinterpret_cast<const __half2*>(&v);
    #pragma unroll
    for (int j = 0; j < 4; j++) {
        float2 f = __half22float2(hp[j]);
        acc[2*j]   += w * f.x;
        acc[2*j+1] += w * f.y;
    }
}

// CSR gather (fp16 rows) + self-loop + bias + tanh (+ fused pooling)
template <bool POOL>
__global__ void k_gather64(const float* __restrict__ b, const int* __restrict__ batch) {
    int t = blockIdx.x * blockDim.x + threadIdx.x;
    int n = t >> 3, c = t & 7;
    if (n >= NN) return;
    int rp = g_rp[n], dg = g_degi[n];
    float dn = g_dinv[n];
    const uint4* hw = reinterpret_cast<const uint4*>(g_hw2);   // 8 uint4 per row
    float acc[8] = {0,0,0,0,0,0,0,0};
    acc_row(acc, hw[n*8 + c], dn*dn);                          // self-loop
    int j = 0;
    for (; j + 1 < dg; j += 2) {
        int2 p0 = g_ep[rp + j];
        int2 p1 = g_ep[rp + j + 1];
        uint4 v0 = hw[p0.x*8 + c];
        uint4 v1 = hw[p1.x*8 + c];
        acc_row(acc, v0, __int_as_float(p0.y));
        acc_row(acc, v1, __int_as_float(p1.y));
    }
    if (j < dg) {
        int2 p0 = g_ep[rp + j];
        acc_row(acc, hw[p0.x*8 + c], __int_as_float(p0.y));
    }
    float4 bb0 = reinterpret_cast<const float4*>(b)[c*2];
    float4 bb1 = reinterpret_cast<const float4*>(b)[c*2 + 1];
    float r[8];
    r[0] = tanhf(acc[0] + bb0.x); r[1] = tanhf(acc[1] + bb0.y);
    r[2] = tanhf(acc[2] + bb0.z); r[3] = tanhf(acc[3] + bb0.w);
    r[4] = tanhf(acc[4] + bb1.x); r[5] = tanhf(acc[5] + bb1.y);
    r[6] = tanhf(acc[6] + bb1.z); r[7] = tanhf(acc[7] + bb1.w);
    __half2 o[4];
    #pragma unroll
    for (int k = 0; k < 4; k++) o[k] = __floats2half2_rn(r[2*k], r[2*k+1]);
    reinterpret_cast<uint4*>(g_h2)[n*8 + c] = *reinterpret_cast<uint4*>(o);
    if (POOL) {
        int g = batch[n];
        int base = g*DD + c*8;
        #pragma unroll
        for (int k = 0; k < 8; k++) {
            atomicMax(&g_gmax[base + k], fkey(r[k]));
            atomicAdd(&g_gsum[base + k], r[k]);
        }
        if (c == 0) atomicAdd(&g_gcnt[g], 1.0f);
    }
}

__global__ void k_out(const float* __restrict__ Wout, const float* __restrict__ bout,
                      float* __restrict__ out) {
    int g = blockIdx.x * blockDim.x + threadIdx.x;
    if (g >= NG) return;
    float cnt = fmaxf(g_gcnt[g], 1.0f);
    float s = bout[0];
    #pragma unroll
    for (int d = 0; d < DD; d++) {
        s += funkey(g_gmax[g*DD + d]) * Wout[d]
           + (g_gsum[g*DD + d] / cnt) * Wout[DD + d];
    }
    out[g] = s;
}

extern "C" void kernel_launch(void* const* d_in, const int* in_sizes, int n_in,
                              void* d_out, int out_size) {
    const float* x     = (const float*)d_in[0];
    const int*   eidx  = (const int*)  d_in[1];
    const int*   batch = (const int*)  d_in[2];
    const float* W0 = (const float*)d_in[3];  const float* b0 = (const float*)d_in[4];
    const float* W1 = (const float*)d_in[5];  const float* b1 = (const float*)d_in[6];
    const float* W2 = (const float*)d_in[7];  const float* b2 = (const float*)d_in[8];
    const float* W3 = (const float*)d_in[9];  const float* b3 = (const float*)d_in[10];
    const float* Wout = (const float*)d_in[11];
    const float* bout = (const float*)d_in[12];
    float* out = (float*)d_out;

    const int* src = eidx;
    const int* dst = eidx + NE;

    // ---- CSR build ----
    k_init <<<(NG*DD + 255) / 256, 256>>>();
    k_deg  <<<(NE/4 + 255) / 256, 256>>>((const int4*)dst);
    k_scan1<<<SCAN_BLKS, 256>>>();
    k_scan3<<<SCAN_BLKS, 256>>>();
    k_fill <<<(NE + 255) / 256, 256>>>(src, dst);

    const int g9_blocks  = (NN * 16 + 255) / 256;  // 3125
    const int g64_blocks = (NN * 8  + 255) / 256;  // 1563
    const int gm_blocks  = (NN + 31) / 32;         // 1563

    // layer 0: aggregate-then-transform
    k_gather9<<<g9_blocks, 256>>>(x);
    k_gemm0f <<<(NN + 7) / 8, 256>>>(W0, b0);
    // layers 1-3
    k_gemm64  <<<gm_blocks, 256>>>(W1);
    k_gather64<false><<<g64_blocks, 256>>>(b1, batch);
    k_gemm64  <<<gm_blocks, 256>>>(W2);
    k_gather64<false><<<g64_blocks, 256>>>(b2, batch);
    k_gemm64  <<<gm_blocks, 256>>>(W3);
    k_gather64<true> <<<g64_blocks, 256>>>(b3, batch);

    k_out<<<(NG + 255) / 256, 256>>>(Wout, bout, out);
}

// round 5
// speedup vs baseline: 1.3770x; 1.3770x over previous
#include <cuda_runtime.h>

#define NN 50000
#define NE 800000
#define NG 1024
#define DIN 9
#define DD 64
#define SCAN_BLKS ((NN + 255) / 256)   // 196
#define GMN 64                          // nodes per gemm64 block

// ---- scratch (static device globals) ----
__device__ float    g_h  [NN*DD];     // activations (post-tanh)
__device__ float    g_hw [NN*DD];     // h @ W
__device__ float    g_aggx[NN*DIN];   // aggregated raw features (layer 0)
__device__ int      g_degi[NN];       // in-degree (no self loop)
__device__ float    g_dinv[NN];
__device__ int      g_rp  [NN];       // CSR row start
__device__ int      g_cur [NN];       // fill cursor
__device__ int2     g_ep  [NE];       // (src, bitcast norm)
__device__ int      g_bsum[256];
__device__ unsigned g_gmax[NG*DD];
__device__ float    g_gsum[NG*DD];
__device__ float    g_gcnt[NG];

__device__ __forceinline__ unsigned fkey(float f) {
    unsigned b = __float_as_uint(f);
    return (b & 0x80000000u) ? ~b : (b | 0x80000000u);
}
__device__ __forceinline__ float funkey(unsigned k) {
    unsigned b = (k & 0x80000000u) ? (k & 0x7FFFFFFFu) : ~k;
    return __uint_as_float(b);
}

__global__ void k_init() {
    int i = blockIdx.x * blockDim.x + threadIdx.x;
    if (i < NN) g_degi[i] = 0;
    if (i < NG*DD) { g_gmax[i] = 0u; g_gsum[i] = 0.0f; }
    if (i < NG) g_gcnt[i] = 0.0f;
}

__global__ void k_deg(const int4* __restrict__ dst4) {
    int e = blockIdx.x * blockDim.x + threadIdx.x;
    if (e >= NE/4) return;
    int4 d = dst4[e];
    atomicAdd(&g_degi[d.x], 1);
    atomicAdd(&g_degi[d.y], 1);
    atomicAdd(&g_degi[d.z], 1);
    atomicAdd(&g_degi[d.w], 1);
}

__global__ void k_scan1() {
    __shared__ int sh[256];
    int t = threadIdx.x, i = blockIdx.x * 256 + t;
    int v = (i < NN) ? g_degi[i] : 0;
    sh[t] = v; __syncthreads();
    #pragma unroll
    for (int off = 1; off < 256; off <<= 1) {
        int u = (t >= off) ? sh[t - off] : 0;
        __syncthreads();
        sh[t] += u; __syncthreads();
    }
    if (i < NN) g_rp[i] = sh[t] - v;
    if (t == 255) g_bsum[blockIdx.x] = sh[255];
}

// fused: per-block prefix of bsum + apply + cursor/dinv init
__global__ void k_scan3() {
    __shared__ int sh[256];
    int t = threadIdx.x;
    int v = (t < SCAN_BLKS) ? g_bsum[t] : 0;
    sh[t] = v; __syncthreads();
    #pragma unroll
    for (int off = 1; off < 256; off <<= 1) {
        int u = (t >= off) ? sh[t - off] : 0;
        __syncthreads();
        sh[t] += u; __syncthreads();
    }
    int boff = (blockIdx.x > 0) ? sh[blockIdx.x - 1] : 0;
    int i = blockIdx.x * 256 + t;
    if (i < NN) {
        g_rp[i] += boff;
        g_cur[i] = 0;
        g_dinv[i] = rsqrtf(1.0f + (float)g_degi[i]);
    }
}

__global__ void k_fill(const int* __restrict__ src, const int* __restrict__ dst) {
    int e = blockIdx.x * blockDim.x + threadIdx.x;
    if (e >= NE) return;
    int d = dst[e], s = src[e];
    int pos = g_rp[d] + atomicAdd(&g_cur[d], 1);
    g_ep[pos] = make_int2(s, __float_as_int(g_dinv[s] * g_dinv[d]));
}

// layer-0 aggregation over raw fp32 features (9 dims), 16 lanes/node, 2-way unroll
__global__ void k_gather9(const float* __restrict__ x) {
    int t = blockIdx.x * blockDim.x + threadIdx.x;
    int n = t >> 4, c = t & 15;
    if (n >= NN || c >= DIN) return;
    int rp = g_rp[n], dg = g_degi[n];
    float dn = g_dinv[n];
    float a0 = dn * dn * x[n*DIN + c];
    float a1 = 0.0f;
    int j = 0;
    for (; j + 2 <= dg; j += 2) {
        int2 p0 = g_ep[rp + j];
        int2 p1 = g_ep[rp + j + 1];
        float v0 = x[p0.x*DIN + c];
        float v1 = x[p1.x*DIN + c];
        a0 += __int_as_float(p0.y) * v0;
        a1 += __int_as_float(p1.y) * v1;
    }
    if (j < dg) {
        int2 p0 = g_ep[rp + j];
        a0 += __int_as_float(p0.y) * x[p0.x*DIN + c];
    }
    g_aggx[n*DIN + c] = a0 + a1;
}

// h0 = tanh(aggx @ W0 + b0); 8 nodes/block, lane computes 2 cols
__global__ void k_gemm0f(const float* __restrict__ W, const float* __restrict__ b) {
    __shared__ float Ws[DIN*DD];
    __shared__ float axs[8][DIN];
    int tid = threadIdx.x;
    for (int i = tid; i < DIN*DD; i += 256) Ws[i] = W[i];
    int nb = blockIdx.x * 8;
    if (tid < 8*DIN) {
        int r = tid / DIN, k = tid % DIN, n = nb + r;
        axs[r][k] = (n < NN) ? g_aggx[n*DIN + k] : 0.0f;
    }
    __syncthreads();
    int r = tid >> 5, l = tid & 31;
    int n = nb + r;
    if (n >= NN) return;
    int c0 = 2*l, c1 = 2*l + 1;
    float s0 = b[c0], s1 = b[c1];
    #pragma unroll
    for (int k = 0; k < DIN; k++) {
        float a = axs[r][k];
        s0 += a * Ws[k*DD + c0];
        s1 += a * Ws[k*DD + c1];
    }
    float2* out = reinterpret_cast<float2*>(&g_h[n*DD + c0]);
    *out = make_float2(tanhf(s0), tanhf(s1));
}

// hw = h @ W, fp32, register-blocked: 64 nodes/block, thread = 2 rows x 8 cols
__global__ void k_gemm64(const float* __restrict__ W) {
    __shared__ float Ws[DD*DD];          // 16 KB
    __shared__ float hs[DD][GMN + 4];    // transposed [k][n], pitch 68 -> 17.4 KB
    int tid = threadIdx.x;
    #pragma unroll
    for (int i = 0; i < 16; i++) Ws[tid + i*256] = W[tid + i*256];
    int nb = blockIdx.x * GMN;
    #pragma unroll
    for (int i = 0; i < 16; i++) {
        int idx = tid + i*256;           // 0..4095
        int n = idx >> 6, k = idx & 63;
        int gn = nb + n;
        hs[k][n] = (gn < NN) ? g_h[gn*DD + k] : 0.0f;
    }
    __syncthreads();
    int q  = tid & 7;          // col group: cols q*8..q*8+7
    int rg = tid >> 3;         // 0..31 -> nodes 2*rg, 2*rg+1
    int n0 = 2*rg;
    float acc0[8] = {0,0,0,0,0,0,0,0};
    float acc1[8] = {0,0,0,0,0,0,0,0};
    #pragma unroll
    for (int k = 0; k < DD; k++) {
        float2 h2 = *reinterpret_cast<const float2*>(&hs[k][n0]);
        const float4* wr = reinterpret_cast<const float4*>(&Ws[k*DD + q*8]);
        float4 w0 = wr[0], w1 = wr[1];
        acc0[0] += h2.x*w0.x; acc0[1] += h2.x*w0.y; acc0[2] += h2.x*w0.z; acc0[3] += h2.x*w0.w;
        acc0[4] += h2.x*w1.x; acc0[5] += h2.x*w1.y; acc0[6] += h2.x*w1.z; acc0[7] += h2.x*w1.w;
        acc1[0] += h2.y*w0.x; acc1[1] += h2.y*w0.y; acc1[2] += h2.y*w0.z; acc1[3] += h2.y*w0.w;
        acc1[4] += h2.y*w1.x; acc1[5] += h2.y*w1.y; acc1[6] += h2.y*w1.z; acc1[7] += h2.y*w1.w;
    }
    int gn0 = nb + n0;
    if (gn0 < NN) {
        float4* o = reinterpret_cast<float4*>(&g_hw[gn0*DD + q*8]);
        o[0] = make_float4(acc0[0], acc0[1], acc0[2], acc0[3]);
        o[1] = make_float4(acc0[4], acc0[5], acc0[6], acc0[7]);
    }
    if (gn0 + 1 < NN) {
        float4* o = reinterpret_cast<float4*>(&g_hw[(gn0+1)*DD + q*8]);
        o[0] = make_float4(acc1[0], acc1[1], acc1[2], acc1[3]);
        o[1] = make_float4(acc1[4], acc1[5], acc1[6], acc1[7]);
    }
}

// CSR gather, warp-per-node: lane owns float2; 4-edge unroll; fused bias+tanh (+pool)
template <bool POOL>
__global__ void k_gather64(const float* __restrict__ b, const int* __restrict__ batch) {
    int n = (blockIdx.x * blockDim.x + threadIdx.x) >> 5;
    int lane = threadIdx.x & 31;
    if (n >= NN) return;
    int rp = g_rp[n], dg = g_degi[n];
    float dn = g_dinv[n];
    const float2* hw2 = reinterpret_cast<const float2*>(g_hw);
    float2 self = hw2[n*32 + lane];
    float d2 = dn * dn;
    float ax = d2 * self.x, ay = d2 * self.y;
    int j = 0;
    for (; j + 4 <= dg; j += 4) {
        int2 p0 = g_ep[rp + j + 0];
        int2 p1 = g_ep[rp + j + 1];
        int2 p2 = g_ep[rp + j + 2];
        int2 p3 = g_ep[rp + j + 3];
        float2 v0 = hw2[p0.x*32 + lane];
        float2 v1 = hw2[p1.x*32 + lane];
        float2 v2 = hw2[p2.x*32 + lane];
        float2 v3 = hw2[p3.x*32 + lane];
        ax += __int_as_float(p0.y)*v0.x; ay += __int_as_float(p0.y)*v0.y;
        ax += __int_as_float(p1.y)*v1.x; ay += __int_as_float(p1.y)*v1.y;
        ax += __int_as_float(p2.y)*v2.x; ay += __int_as_float(p2.y)*v2.y;
        ax += __int_as_float(p3.y)*v3.x; ay += __int_as_float(p3.y)*v3.y;
    }
    for (; j < dg; j++) {
        int2 p0 = g_ep[rp + j];
        float2 v0 = hw2[p0.x*32 + lane];
        ax += __int_as_float(p0.y)*v0.x; ay += __int_as_float(p0.y)*v0.y;
    }
    float2 bb = reinterpret_cast<const float2*>(b)[lane];
    float rx = tanhf(ax + bb.x);
    float ry = tanhf(ay + bb.y);
    reinterpret_cast<float2*>(g_h)[n*32 + lane] = make_float2(rx, ry);
    if (POOL) {
        int g = batch[n];
        int base = g*DD + 2*lane;
        atomicMax(&g_gmax[base + 0], fkey(rx));
        atomicMax(&g_gmax[base + 1], fkey(ry));
        atomicAdd(&g_gsum[base + 0], rx);
        atomicAdd(&g_gsum[base + 1], ry);
        if (lane == 0) atomicAdd(&g_gcnt[g], 1.0f);
    }
}

// warp-per-graph output head
__global__ void k_out(const float* __restrict__ Wout, const float* __restrict__ bout,
                      float* __restrict__ out) {
    int g = (blockIdx.x * blockDim.x + threadIdx.x) >> 5;
    int lane = threadIdx.x & 31;
    if (g >= NG) return;
    float cnt = fmaxf(g_gcnt[g], 1.0f);
    float s = 0.0f;
    #pragma unroll
    for (int d = lane; d < DD; d += 32) {
        s += funkey(g_gmax[g*DD + d]) * Wout[d]
           + (g_gsum[g*DD + d] / cnt) * Wout[DD + d];
    }
    #pragma unroll
    for (int o = 16; o > 0; o >>= 1) s += __shfl_down_sync(0xFFFFFFFFu, s, o);
    if (lane == 0) out[g] = s + bout[0];
}

extern "C" void kernel_launch(void* const* d_in, const int* in_sizes, int n_in,
                              void* d_out, int out_size) {
    const float* x     = (const float*)d_in[0];
    const int*   eidx  = (const int*)  d_in[1];
    const int*   batch = (const int*)  d_in[2];
    const float* W0 = (const float*)d_in[3];  const float* b0 = (const float*)d_in[4];
    const float* W1 = (const float*)d_in[5];  const float* b1 = (const float*)d_in[6];
    const float* W2 = (const float*)d_in[7];  const float* b2 = (const float*)d_in[8];
    const float* W3 = (const float*)d_in[9];  const float* b3 = (const float*)d_in[10];
    const float* Wout = (const float*)d_in[11];
    const float* bout = (const float*)d_in[12];
    float* out = (float*)d_out;

    const int* src = eidx;
    const int* dst = eidx + NE;

    // ---- CSR build ----
    k_init <<<(NG*DD + 255) / 256, 256>>>();
    k_deg  <<<(NE/4 + 255) / 256, 256>>>((const int4*)dst);
    k_scan1<<<SCAN_BLKS, 256>>>();
    k_scan3<<<SCAN_BLKS, 256>>>();
    k_fill <<<(NE + 255) / 256, 256>>>(src, dst);

    const int g9_blocks  = (NN * 16 + 255) / 256;  // 3125
    const int g64_blocks = (NN * 32 + 255) / 256;  // 6250 (warp per node)
    const int gm_blocks  = (NN + GMN - 1) / GMN;   // 782

    // layer 0: aggregate-then-transform
    k_gather9<<<g9_blocks, 256>>>(x);
    k_gemm0f <<<(NN + 7) / 8, 256>>>(W0, b0);
    // layers 1-3
    k_gemm64  <<<gm_blocks, 256>>>(W1);
    k_gather64<false><<<g64_blocks, 256>>>(b1, batch);
    k_gemm64  <<<gm_blocks, 256>>>(W2);
    k_gather64<false><<<g64_blocks, 256>>>(b2, batch);
    k_gemm64  <<<gm_blocks, 256>>>(W3);
    k_gather64<true> <<<g64_blocks, 256>>>(b3, batch);

    k_out<<<(NG*32 + 255) / 256, 256>>>(Wout, bout, out);
}